// round 1
// baseline (speedup 1.0000x reference)
#include <cuda_runtime.h>
#include <cuda_bf16.h>

#define N_NODES 200000
#define N_EDGES 6400000
#define N_LAYERS 3

// Scratch (no cudaMalloc allowed)
__device__ float  g_A0[N_NODES];
__device__ float  g_A1[N_NODES];
__device__ float2 g_P[N_NODES];
// per-layer: [0..11]=W row, [12]=b, [13]=sum(w[0:4]), [14]=sum(w[4:8])
__device__ float  g_wc[N_LAYERS * 16];

// ---------------------------------------------------------------------------
// 1. Tiny kernel: precompute per-layer weight constants
// ---------------------------------------------------------------------------
__global__ void prep_consts_kernel(const float* __restrict__ W,
                                   const float* __restrict__ b) {
    int i = threadIdx.x;   // layer
    if (i >= N_LAYERS) return;
    float sA = 0.f, sB = 0.f;
    #pragma unroll
    for (int j = 0; j < 12; j++) {
        float w = W[i * 12 + j];
        g_wc[i * 16 + j] = w;
        if (j < 4)            sA += w;
        else if (j < 8)       sB += w;
    }
    g_wc[i * 16 + 12] = b[i];
    g_wc[i * 16 + 13] = sA;
    g_wc[i * 16 + 14] = sB;
}

// ---------------------------------------------------------------------------
// 2. Zero the first accumulator
// ---------------------------------------------------------------------------
__global__ void zero_A_kernel(float* __restrict__ A) {
    int n = blockIdx.x * blockDim.x + threadIdx.x;
    if (n < N_NODES) A[n] = 0.f;
}

// ---------------------------------------------------------------------------
// 3. Per-layer node prep: P[n] = (ws·z0[n] + sA*A[n], wd·z0[n] + sB*A[n])
//    and carry accumulator forward: Aw[n] = Ar[n]
// ---------------------------------------------------------------------------
__global__ void node_prep_kernel(const float4* __restrict__ z0,
                                 const float* __restrict__ Ar,
                                 float* __restrict__ Aw,
                                 float2* __restrict__ P,
                                 int layer) {
    int n = blockIdx.x * blockDim.x + threadIdx.x;
    if (n >= N_NODES) return;
    const float* wc = g_wc + layer * 16;
    float4 z = z0[n];
    float  a = Ar[n];
    Aw[n] = a;
    float gs = wc[0]*z.x + wc[1]*z.y + wc[2]*z.z + wc[3]*z.w + wc[13]*a;
    float gd = wc[4]*z.x + wc[5]*z.y + wc[6]*z.z + wc[7]*z.w + wc[14]*a;
    P[n] = make_float2(gs, gd);
}

// ---------------------------------------------------------------------------
// 4. Edge kernel: 4 edges per thread, vectorized streaming loads,
//    two 8B random gathers per edge, one RED.ADD per edge.
// ---------------------------------------------------------------------------
__global__ void __launch_bounds__(256)
edge_kernel(const int4* __restrict__ src4,
            const int4* __restrict__ dst4,
            const float4* __restrict__ r4,
            const float4* __restrict__ rhat4,
            const float2* __restrict__ P,
            float* __restrict__ Aw,
            int layer) {
    int t = blockIdx.x * blockDim.x + threadIdx.x;
    if (t >= N_EDGES / 4) return;

    const float* wc = g_wc + layer * 16;
    const float w8  = __ldg(wc + 8);
    const float w9  = __ldg(wc + 9);
    const float w10 = __ldg(wc + 10);
    const float w11 = __ldg(wc + 11);
    const float bb  = __ldg(wc + 12);

    int4   s  = __ldg(src4 + t);
    int4   d  = __ldg(dst4 + t);
    float4 r  = __ldg(r4   + t);
    float4 h0 = __ldg(rhat4 + 3 * t + 0);
    float4 h1 = __ldg(rhat4 + 3 * t + 1);
    float4 h2 = __ldg(rhat4 + 3 * t + 2);

    float2 Ps0 = __ldg(&P[s.x]);
    float2 Ps1 = __ldg(&P[s.y]);
    float2 Ps2 = __ldg(&P[s.z]);
    float2 Ps3 = __ldg(&P[s.w]);
    float2 Pd0 = __ldg(&P[d.x]);
    float2 Pd1 = __ldg(&P[d.y]);
    float2 Pd2 = __ldg(&P[d.z]);
    float2 Pd3 = __ldg(&P[d.w]);

    // edge 0: rhat = (h0.x, h0.y, h0.z)
    float m0 = Ps0.x + Pd0.y + bb + w8 * r.x + w9 * h0.x + w10 * h0.y + w11 * h0.z;
    // edge 1: rhat = (h0.w, h1.x, h1.y)
    float m1 = Ps1.x + Pd1.y + bb + w8 * r.y + w9 * h0.w + w10 * h1.x + w11 * h1.y;
    // edge 2: rhat = (h1.z, h1.w, h2.x)
    float m2 = Ps2.x + Pd2.y + bb + w8 * r.z + w9 * h1.z + w10 * h1.w + w11 * h2.x;
    // edge 3: rhat = (h2.y, h2.z, h2.w)
    float m3 = Ps3.x + Pd3.y + bb + w8 * r.w + w9 * h2.y + w10 * h2.z + w11 * h2.w;

    atomicAdd(&Aw[d.x], m0);
    atomicAdd(&Aw[d.y], m1);
    atomicAdd(&Aw[d.z], m2);
    atomicAdd(&Aw[d.w], m3);
}

// ---------------------------------------------------------------------------
// 5. Finalize: out_z = z0 + A (broadcast), out_x = z0
// ---------------------------------------------------------------------------
__global__ void finalize_kernel(const float4* __restrict__ z0,
                                const float* __restrict__ A,
                                float4* __restrict__ out) {
    int n = blockIdx.x * blockDim.x + threadIdx.x;
    if (n >= N_NODES) return;
    float4 z = z0[n];
    float  a = A[n];
    out[n] = make_float4(z.x + a, z.y + a, z.z + a, z.w + a);
    out[N_NODES + n] = z;   // x = original z
}

// ---------------------------------------------------------------------------
extern "C" void kernel_launch(void* const* d_in, const int* in_sizes, int n_in,
                              void* d_out, int out_size) {
    const float* z    = (const float*)d_in[0];
    const float* r    = (const float*)d_in[1];
    const float* rhat = (const float*)d_in[2];
    const float* W    = (const float*)d_in[3];
    const float* b    = (const float*)d_in[4];
    const int*   src  = (const int*)d_in[5];
    const int*   dst  = (const int*)d_in[6];
    float* out = (float*)d_out;

    float*  A0; cudaGetSymbolAddress((void**)&A0, g_A0);
    float*  A1; cudaGetSymbolAddress((void**)&A1, g_A1);
    float2* P;  cudaGetSymbolAddress((void**)&P,  g_P);

    const int NODE_BLOCKS = (N_NODES + 255) / 256;
    const int EDGE_BLOCKS = (N_EDGES / 4 + 255) / 256;

    prep_consts_kernel<<<1, 32>>>(W, b);
    zero_A_kernel<<<NODE_BLOCKS, 256>>>(A0);

    float* Ar = A0;
    float* Aw = A1;
    for (int layer = 0; layer < N_LAYERS; layer++) {
        node_prep_kernel<<<NODE_BLOCKS, 256>>>((const float4*)z, Ar, Aw, P, layer);
        edge_kernel<<<EDGE_BLOCKS, 256>>>((const int4*)src, (const int4*)dst,
                                          (const float4*)r, (const float4*)rhat,
                                          P, Aw, layer);
        float* tmp = Ar; Ar = Aw; Aw = tmp;
    }
    // After the loop, Ar holds the final cumulative scalar.
    finalize_kernel<<<NODE_BLOCKS, 256>>>((const float4*)z, Ar, (float4*)out);
}

// round 2
// speedup vs baseline: 1.0471x; 1.0471x over previous
#include <cuda_runtime.h>
#include <cuda_bf16.h>

#define N_NODES 200000
#define N_EDGES 6400000
#define N_LAYERS 3

// Scratch (no cudaMalloc allowed)
__device__ float g_A[N_NODES];     // cumulative per-node scalar
__device__ float g_S[N_NODES];     // per-layer scatter accumulator
__device__ float g_Ps[N_NODES];    // per-layer src-side node scalar
__device__ float g_deg[N_NODES];   // in-degree (float)
__device__ float g_C0[N_EDGES];    // per-edge geometry constant, layer 0
__device__ float g_C1[N_EDGES];
__device__ float g_C2[N_EDGES];
// per-layer: [0..11]=W row, [12]=b, [13]=sum(w[0:4]) (=sA), [14]=sum(w[4:8]) (=sB)
__device__ float g_wc[N_LAYERS * 16];

// ---------------------------------------------------------------------------
__global__ void prep_consts_kernel(const float* __restrict__ W,
                                   const float* __restrict__ b) {
    int i = threadIdx.x;
    if (i >= N_LAYERS) return;
    float sA = 0.f, sB = 0.f;
    #pragma unroll
    for (int j = 0; j < 12; j++) {
        float w = W[i * 12 + j];
        g_wc[i * 16 + j] = w;
        if (j < 4)       sA += w;
        else if (j < 8)  sB += w;
    }
    g_wc[i * 16 + 12] = b[i];
    g_wc[i * 16 + 13] = sA;
    g_wc[i * 16 + 14] = sB;
}

// ---------------------------------------------------------------------------
__global__ void zero_kernel(float* __restrict__ A, float* __restrict__ deg) {
    int n = blockIdx.x * blockDim.x + threadIdx.x;
    if (n < N_NODES) { A[n] = 0.f; deg[n] = 0.f; }
}

// ---------------------------------------------------------------------------
// One streaming pass: per-edge geometry constants for all 3 layers + in-degree
// ---------------------------------------------------------------------------
__global__ void __launch_bounds__(256)
geom_deg_kernel(const int4* __restrict__ dst4,
                const float4* __restrict__ r4,
                const float4* __restrict__ rhat4,
                float4* __restrict__ C0,
                float4* __restrict__ C1,
                float4* __restrict__ C2,
                float* __restrict__ deg) {
    int t = blockIdx.x * blockDim.x + threadIdx.x;
    if (t >= N_EDGES / 4) return;

    int4   d  = __ldg(dst4 + t);
    float4 r  = __ldg(r4   + t);
    float4 h0 = __ldg(rhat4 + 3 * t + 0);
    float4 h1 = __ldg(rhat4 + 3 * t + 1);
    float4 h2 = __ldg(rhat4 + 3 * t + 2);

    // per-edge rhat triples
    float rh[4][3] = {{h0.x, h0.y, h0.z}, {h0.w, h1.x, h1.y},
                      {h1.z, h1.w, h2.x}, {h2.y, h2.z, h2.w}};
    float rr[4] = {r.x, r.y, r.z, r.w};

    float4* Cs[3] = {C0, C1, C2};
    #pragma unroll
    for (int l = 0; l < N_LAYERS; l++) {
        const float* wc = g_wc + l * 16;
        float w8 = __ldg(wc + 8),  w9 = __ldg(wc + 9);
        float wa = __ldg(wc + 10), wb = __ldg(wc + 11);
        float bb = __ldg(wc + 12);
        float4 c;
        c.x = bb + w8 * rr[0] + w9 * rh[0][0] + wa * rh[0][1] + wb * rh[0][2];
        c.y = bb + w8 * rr[1] + w9 * rh[1][0] + wa * rh[1][1] + wb * rh[1][2];
        c.z = bb + w8 * rr[2] + w9 * rh[2][0] + wa * rh[2][1] + wb * rh[2][2];
        c.w = bb + w8 * rr[3] + w9 * rh[3][0] + wa * rh[3][1] + wb * rh[3][2];
        Cs[l][t] = c;
    }

    atomicAdd(&deg[d.x], 1.f);
    atomicAdd(&deg[d.y], 1.f);
    atomicAdd(&deg[d.z], 1.f);
    atomicAdd(&deg[d.w], 1.f);
}

// ---------------------------------------------------------------------------
// Per-layer node prep: Ps[n] = ws.z0[n] + sA*A[n], and zero S[n]
// ---------------------------------------------------------------------------
__global__ void node_prep_kernel(const float4* __restrict__ z0,
                                 const float* __restrict__ A,
                                 float* __restrict__ Ps,
                                 float* __restrict__ S,
                                 int layer) {
    int n = blockIdx.x * blockDim.x + threadIdx.x;
    if (n >= N_NODES) return;
    const float* wc = g_wc + layer * 16;
    float4 z = z0[n];
    float  a = A[n];
    Ps[n] = wc[0]*z.x + wc[1]*z.y + wc[2]*z.z + wc[3]*z.w + wc[13]*a;
    S[n] = 0.f;
}

// ---------------------------------------------------------------------------
// Per-layer edge pass: S[dst] += Ps[src] + c_e
// (the Pd[dst] term is folded out: handled as deg[n]*Pd[n] in node_update)
// ---------------------------------------------------------------------------
__global__ void __launch_bounds__(256)
edge_kernel(const int4* __restrict__ src4,
            const int4* __restrict__ dst4,
            const float4* __restrict__ C,
            const float* __restrict__ Ps,
            float* __restrict__ S) {
    int t = blockIdx.x * blockDim.x + threadIdx.x;
    if (t >= N_EDGES / 4) return;

    int4   s = __ldg(src4 + t);
    int4   d = __ldg(dst4 + t);
    float4 c = __ldg(C + t);

    float p0 = __ldg(&Ps[s.x]);
    float p1 = __ldg(&Ps[s.y]);
    float p2 = __ldg(&Ps[s.z]);
    float p3 = __ldg(&Ps[s.w]);

    atomicAdd(&S[d.x], p0 + c.x);
    atomicAdd(&S[d.y], p1 + c.y);
    atomicAdd(&S[d.z], p2 + c.z);
    atomicAdd(&S[d.w], p3 + c.w);
}

// ---------------------------------------------------------------------------
// Per-layer node update: A += S + deg * (wd.z0 + sB*A_old)
// ---------------------------------------------------------------------------
__global__ void node_update_kernel(const float4* __restrict__ z0,
                                   const float* __restrict__ S,
                                   const float* __restrict__ deg,
                                   float* __restrict__ A,
                                   int layer) {
    int n = blockIdx.x * blockDim.x + threadIdx.x;
    if (n >= N_NODES) return;
    const float* wc = g_wc + layer * 16;
    float4 z = z0[n];
    float  a = A[n];
    float pd = wc[4]*z.x + wc[5]*z.y + wc[6]*z.z + wc[7]*z.w + wc[14]*a;
    A[n] = a + S[n] + deg[n] * pd;
}

// ---------------------------------------------------------------------------
__global__ void finalize_kernel(const float4* __restrict__ z0,
                                const float* __restrict__ A,
                                float4* __restrict__ out) {
    int n = blockIdx.x * blockDim.x + threadIdx.x;
    if (n >= N_NODES) return;
    float4 z = z0[n];
    float  a = A[n];
    out[n] = make_float4(z.x + a, z.y + a, z.z + a, z.w + a);
    out[N_NODES + n] = z;
}

// ---------------------------------------------------------------------------
extern "C" void kernel_launch(void* const* d_in, const int* in_sizes, int n_in,
                              void* d_out, int out_size) {
    const float* z    = (const float*)d_in[0];
    const float* r    = (const float*)d_in[1];
    const float* rhat = (const float*)d_in[2];
    const float* W    = (const float*)d_in[3];
    const float* b    = (const float*)d_in[4];
    const int*   src  = (const int*)d_in[5];
    const int*   dst  = (const int*)d_in[6];
    float* out = (float*)d_out;

    float *A, *S, *Ps, *deg, *C0, *C1, *C2;
    cudaGetSymbolAddress((void**)&A,   g_A);
    cudaGetSymbolAddress((void**)&S,   g_S);
    cudaGetSymbolAddress((void**)&Ps,  g_Ps);
    cudaGetSymbolAddress((void**)&deg, g_deg);
    cudaGetSymbolAddress((void**)&C0,  g_C0);
    cudaGetSymbolAddress((void**)&C1,  g_C1);
    cudaGetSymbolAddress((void**)&C2,  g_C2);
    float* Cs[3] = {C0, C1, C2};

    const int NODE_BLOCKS = (N_NODES + 255) / 256;
    const int EDGE_BLOCKS = (N_EDGES / 4 + 255) / 256;

    prep_consts_kernel<<<1, 32>>>(W, b);
    zero_kernel<<<NODE_BLOCKS, 256>>>(A, deg);
    geom_deg_kernel<<<EDGE_BLOCKS, 256>>>((const int4*)dst, (const float4*)r,
                                          (const float4*)rhat,
                                          (float4*)C0, (float4*)C1, (float4*)C2,
                                          deg);

    for (int layer = 0; layer < N_LAYERS; layer++) {
        node_prep_kernel<<<NODE_BLOCKS, 256>>>((const float4*)z, A, Ps, S, layer);
        edge_kernel<<<EDGE_BLOCKS, 256>>>((const int4*)src, (const int4*)dst,
                                          (const float4*)Cs[layer], Ps, S);
        node_update_kernel<<<NODE_BLOCKS, 256>>>((const float4*)z, S, deg, A, layer);
    }
    finalize_kernel<<<NODE_BLOCKS, 256>>>((const float4*)z, A, (float4*)out);
}

// round 3
// speedup vs baseline: 1.3863x; 1.3239x over previous
#include <cuda_runtime.h>
#include <cuda_bf16.h>
#include <cstdint>

#define N_NODES 200000
#define N_EDGES 6400000
#define N_LAYERS 3

// Scratch (no cudaMalloc allowed)
__device__ float4 g_T[N_NODES];    // (t0, t1, t2, deg) accumulators
__device__ float  g_A[N_NODES];    // current per-node cumulative scalar
__device__ float  g_q1[N_NODES];   // M @ A_1
__device__ float  g_q2[N_NODES];   // M @ A_2
// per-layer 16 floats: [0..11]=W row, [12]=b, [13]=sA=sum(w[0:4]), [14]=sB=sum(w[4:8])
__device__ float  g_wc[N_LAYERS * 16];

// ---------------------------------------------------------------------------
__global__ void prep_consts_kernel(const float* __restrict__ W,
                                   const float* __restrict__ b) {
    int i = threadIdx.x;
    if (i >= N_LAYERS) return;
    float sA = 0.f, sB = 0.f;
    #pragma unroll
    for (int j = 0; j < 12; j++) {
        float w = W[i * 12 + j];
        g_wc[i * 16 + j] = w;
        if (j < 4)       sA += w;
        else if (j < 8)  sB += w;
    }
    g_wc[i * 16 + 12] = b[i];
    g_wc[i * 16 + 13] = sA;
    g_wc[i * 16 + 14] = sB;
}

// ---------------------------------------------------------------------------
__global__ void zero_kernel(float4* __restrict__ T,
                            float* __restrict__ q1,
                            float* __restrict__ q2) {
    int n = blockIdx.x * blockDim.x + threadIdx.x;
    if (n >= N_NODES) return;
    T[n] = make_float4(0.f, 0.f, 0.f, 0.f);
    q1[n] = 0.f;
    q2[n] = 0.f;
}

// ---------------------------------------------------------------------------
// Vectorized float4 reduction (sm_90+ PTX)
// ---------------------------------------------------------------------------
__device__ __forceinline__ void red_add_v4(float4* ptr, float a, float b,
                                           float c, float d) {
    asm volatile("red.global.add.v4.f32 [%0], {%1, %2, %3, %4};"
                 :: "l"(__cvta_generic_to_global(ptr)),
                    "f"(a), "f"(b), "f"(c), "f"(d)
                 : "memory");
}

// ---------------------------------------------------------------------------
// ONE heavy edge pass for all 3 layers:
//   T[dst] += ( ws_l.z0[src] + w_geo_l.(r,rhat) for l=0..2 , 1 )
// ---------------------------------------------------------------------------
__global__ void __launch_bounds__(256)
heavy_edge_kernel(const int4* __restrict__ src4,
                  const int4* __restrict__ dst4,
                  const float4* __restrict__ r4,
                  const float4* __restrict__ rhat4,
                  const float4* __restrict__ z0,
                  float4* __restrict__ T) {
    int t = blockIdx.x * blockDim.x + threadIdx.x;
    if (t >= N_EDGES / 4) return;

    int4   s  = __ldg(src4 + t);
    int4   d  = __ldg(dst4 + t);
    float4 r  = __ldg(r4   + t);
    float4 h0 = __ldg(rhat4 + 3 * t + 0);
    float4 h1 = __ldg(rhat4 + 3 * t + 1);
    float4 h2 = __ldg(rhat4 + 3 * t + 2);

    float4 zs0 = __ldg(&z0[s.x]);
    float4 zs1 = __ldg(&z0[s.y]);
    float4 zs2 = __ldg(&z0[s.z]);
    float4 zs3 = __ldg(&z0[s.w]);

    float rr[4]    = {r.x, r.y, r.z, r.w};
    float rh[4][3] = {{h0.x, h0.y, h0.z}, {h0.w, h1.x, h1.y},
                      {h1.z, h1.w, h2.x}, {h2.y, h2.z, h2.w}};
    float4 zs[4]   = {zs0, zs1, zs2, zs3};
    int    dd[4]   = {d.x, d.y, d.z, d.w};

    float tv[4][3];
    #pragma unroll
    for (int l = 0; l < N_LAYERS; l++) {
        const float* wc = g_wc + l * 16;
        float w0 = wc[0], w1 = wc[1], w2 = wc[2], w3 = wc[3];
        float w8 = wc[8], w9 = wc[9], wa = wc[10], wb = wc[11];
        #pragma unroll
        for (int e = 0; e < 4; e++) {
            tv[e][l] = w0 * zs[e].x + w1 * zs[e].y + w2 * zs[e].z + w3 * zs[e].w
                     + w8 * rr[e] + w9 * rh[e][0] + wa * rh[e][1] + wb * rh[e][2];
        }
    }

    #pragma unroll
    for (int e = 0; e < 4; e++)
        red_add_v4(&T[dd[e]], tv[e][0], tv[e][1], tv[e][2], 1.f);
}

// ---------------------------------------------------------------------------
// Light edge pass: q[dst] += A[src]
// ---------------------------------------------------------------------------
__global__ void __launch_bounds__(256)
light_edge_kernel(const int4* __restrict__ src4,
                  const int4* __restrict__ dst4,
                  const float* __restrict__ A,
                  float* __restrict__ q) {
    int t = blockIdx.x * blockDim.x + threadIdx.x;
    if (t >= N_EDGES / 4) return;

    int4 s = __ldg(src4 + t);
    int4 d = __ldg(dst4 + t);

    float a0 = __ldg(&A[s.x]);
    float a1 = __ldg(&A[s.y]);
    float a2 = __ldg(&A[s.z]);
    float a3 = __ldg(&A[s.w]);

    atomicAdd(&q[d.x], a0);
    atomicAdd(&q[d.y], a1);
    atomicAdd(&q[d.z], a2);
    atomicAdd(&q[d.w], a3);
}

// ---------------------------------------------------------------------------
// Node update layer 0: A1 = t0 + deg*(b0 + wd0.z0)    (A0 = 0, q0 = 0)
// ---------------------------------------------------------------------------
__global__ void node0_kernel(const float4* __restrict__ z0,
                             const float4* __restrict__ T,
                             float* __restrict__ A) {
    int n = blockIdx.x * blockDim.x + threadIdx.x;
    if (n >= N_NODES) return;
    const float* wc = g_wc;  // layer 0
    float4 z = z0[n];
    float4 tt = T[n];
    float pd = wc[12] + wc[4]*z.x + wc[5]*z.y + wc[6]*z.z + wc[7]*z.w;
    A[n] = tt.x + tt.w * pd;
}

// ---------------------------------------------------------------------------
// Node update layer l (l=1,2): A += t_l + sA_l*q_l + deg*(b_l + wd_l.z0 + sB_l*A)
// ---------------------------------------------------------------------------
__global__ void node_update_kernel(const float4* __restrict__ z0,
                                   const float4* __restrict__ T,
                                   const float* __restrict__ q,
                                   float* __restrict__ A,
                                   int layer) {
    int n = blockIdx.x * blockDim.x + threadIdx.x;
    if (n >= N_NODES) return;
    const float* wc = g_wc + layer * 16;
    float4 z = z0[n];
    float4 tt = T[n];
    float  a = A[n];
    float  tl = (layer == 1) ? tt.y : tt.z;
    float pd = wc[12] + wc[4]*z.x + wc[5]*z.y + wc[6]*z.z + wc[7]*z.w + wc[14]*a;
    A[n] = a + tl + wc[13] * q[n] + tt.w * pd;
}

// ---------------------------------------------------------------------------
__global__ void finalize_kernel(const float4* __restrict__ z0,
                                const float* __restrict__ A,
                                float4* __restrict__ out) {
    int n = blockIdx.x * blockDim.x + threadIdx.x;
    if (n >= N_NODES) return;
    float4 z = z0[n];
    float  a = A[n];
    out[n] = make_float4(z.x + a, z.y + a, z.z + a, z.w + a);
    out[N_NODES + n] = z;
}

// ---------------------------------------------------------------------------
extern "C" void kernel_launch(void* const* d_in, const int* in_sizes, int n_in,
                              void* d_out, int out_size) {
    const float* z    = (const float*)d_in[0];
    const float* r    = (const float*)d_in[1];
    const float* rhat = (const float*)d_in[2];
    const float* W    = (const float*)d_in[3];
    const float* b    = (const float*)d_in[4];
    const int*   src  = (const int*)d_in[5];
    const int*   dst  = (const int*)d_in[6];
    float* out = (float*)d_out;

    float4 *T; float *A, *q1, *q2;
    cudaGetSymbolAddress((void**)&T,  g_T);
    cudaGetSymbolAddress((void**)&A,  g_A);
    cudaGetSymbolAddress((void**)&q1, g_q1);
    cudaGetSymbolAddress((void**)&q2, g_q2);

    const int NODE_BLOCKS = (N_NODES + 255) / 256;
    const int EDGE_BLOCKS = (N_EDGES / 4 + 255) / 256;

    prep_consts_kernel<<<1, 32>>>(W, b);
    zero_kernel<<<NODE_BLOCKS, 256>>>(T, q1, q2);

    heavy_edge_kernel<<<EDGE_BLOCKS, 256>>>((const int4*)src, (const int4*)dst,
                                            (const float4*)r, (const float4*)rhat,
                                            (const float4*)z, T);

    node0_kernel<<<NODE_BLOCKS, 256>>>((const float4*)z, T, A);

    light_edge_kernel<<<EDGE_BLOCKS, 256>>>((const int4*)src, (const int4*)dst, A, q1);
    node_update_kernel<<<NODE_BLOCKS, 256>>>((const float4*)z, T, q1, A, 1);

    light_edge_kernel<<<EDGE_BLOCKS, 256>>>((const int4*)src, (const int4*)dst, A, q2);
    node_update_kernel<<<NODE_BLOCKS, 256>>>((const float4*)z, T, q2, A, 2);

    finalize_kernel<<<NODE_BLOCKS, 256>>>((const float4*)z, A, (float4*)out);
}

// round 4
// speedup vs baseline: 1.3920x; 1.0040x over previous
#include <cuda_runtime.h>
#include <cuda_bf16.h>
#include <cstdint>

#define N_NODES 200000
#define N_EDGES 6400000
#define N_LAYERS 3

// Scratch (no cudaMalloc allowed)
__device__ float4 g_T[N_NODES];    // (t0, t1, t2, deg) accumulators
__device__ float  g_A[N_NODES];    // current per-node cumulative scalar
__device__ float  g_q1[N_NODES];   // M @ A_1
__device__ float  g_q2[N_NODES];   // M @ A_2
// per-layer 16 floats: [0..11]=W row, [12]=b, [13]=sA=sum(w[0:4]), [14]=sB=sum(w[4:8])
__device__ float  g_wc[N_LAYERS * 16];

// ---------------------------------------------------------------------------
// 1. init: zero scratch; block 0 also computes per-layer weight constants
// ---------------------------------------------------------------------------
__global__ void init_kernel(const float* __restrict__ W,
                            const float* __restrict__ b,
                            float4* __restrict__ T,
                            float* __restrict__ q1,
                            float* __restrict__ q2) {
    int n = blockIdx.x * blockDim.x + threadIdx.x;
    if (blockIdx.x == 0 && threadIdx.x < N_LAYERS) {
        int i = threadIdx.x;
        float sA = 0.f, sB = 0.f;
        #pragma unroll
        for (int j = 0; j < 12; j++) {
            float w = W[i * 12 + j];
            g_wc[i * 16 + j] = w;
            if (j < 4)       sA += w;
            else if (j < 8)  sB += w;
        }
        g_wc[i * 16 + 12] = b[i];
        g_wc[i * 16 + 13] = sA;
        g_wc[i * 16 + 14] = sB;
    }
    if (n < N_NODES) {
        T[n] = make_float4(0.f, 0.f, 0.f, 0.f);
        q1[n] = 0.f;
        q2[n] = 0.f;
    }
}

// ---------------------------------------------------------------------------
__device__ __forceinline__ void red_add_v4(float4* ptr, float a, float b,
                                           float c, float d) {
    asm volatile("red.global.add.v4.f32 [%0], {%1, %2, %3, %4};"
                 :: "l"(__cvta_generic_to_global(ptr)),
                    "f"(a), "f"(b), "f"(c), "f"(d)
                 : "memory");
}

// ---------------------------------------------------------------------------
// 2. ONE heavy edge pass for all 3 layers:
//    T[dst] += ( ws_l.z0[src] + w_geo_l.(r,rhat)  for l=0..2 , 1 )
//    Streams use .cs (evict-first) to keep L1 for the z0 gathers.
// ---------------------------------------------------------------------------
__global__ void __launch_bounds__(256)
heavy_edge_kernel(const int4* __restrict__ src4,
                  const int4* __restrict__ dst4,
                  const float4* __restrict__ r4,
                  const float4* __restrict__ rhat4,
                  const float4* __restrict__ z0,
                  float4* __restrict__ T) {
    int t = blockIdx.x * blockDim.x + threadIdx.x;
    if (t >= N_EDGES / 4) return;

    int4   s  = __ldcs(src4 + t);
    int4   d  = __ldcs(dst4 + t);
    float4 r  = __ldcs(r4   + t);
    float4 h0 = __ldcs(rhat4 + 3 * t + 0);
    float4 h1 = __ldcs(rhat4 + 3 * t + 1);
    float4 h2 = __ldcs(rhat4 + 3 * t + 2);

    float4 zs0 = __ldg(&z0[s.x]);
    float4 zs1 = __ldg(&z0[s.y]);
    float4 zs2 = __ldg(&z0[s.z]);
    float4 zs3 = __ldg(&z0[s.w]);

    float rr[4]    = {r.x, r.y, r.z, r.w};
    float rh[4][3] = {{h0.x, h0.y, h0.z}, {h0.w, h1.x, h1.y},
                      {h1.z, h1.w, h2.x}, {h2.y, h2.z, h2.w}};
    float4 zs[4]   = {zs0, zs1, zs2, zs3};
    int    dd[4]   = {d.x, d.y, d.z, d.w};

    float tv[4][3];
    #pragma unroll
    for (int l = 0; l < N_LAYERS; l++) {
        const float* wc = g_wc + l * 16;
        float w0 = wc[0], w1 = wc[1], w2 = wc[2], w3 = wc[3];
        float w8 = wc[8], w9 = wc[9], wa = wc[10], wb = wc[11];
        #pragma unroll
        for (int e = 0; e < 4; e++) {
            tv[e][l] = w0 * zs[e].x + w1 * zs[e].y + w2 * zs[e].z + w3 * zs[e].w
                     + w8 * rr[e] + w9 * rh[e][0] + wa * rh[e][1] + wb * rh[e][2];
        }
    }

    #pragma unroll
    for (int e = 0; e < 4; e++)
        red_add_v4(&T[dd[e]], tv[e][0], tv[e][1], tv[e][2], 1.f);
}

// ---------------------------------------------------------------------------
// 3. Light edge pass: q[dst] += A[src]
// ---------------------------------------------------------------------------
__global__ void __launch_bounds__(256)
light_edge_kernel(const int4* __restrict__ src4,
                  const int4* __restrict__ dst4,
                  const float* __restrict__ A,
                  float* __restrict__ q) {
    int t = blockIdx.x * blockDim.x + threadIdx.x;
    if (t >= N_EDGES / 4) return;

    int4 s = __ldcs(src4 + t);
    int4 d = __ldcs(dst4 + t);

    float a0 = __ldg(&A[s.x]);
    float a1 = __ldg(&A[s.y]);
    float a2 = __ldg(&A[s.z]);
    float a3 = __ldg(&A[s.w]);

    atomicAdd(&q[d.x], a0);
    atomicAdd(&q[d.y], a1);
    atomicAdd(&q[d.z], a2);
    atomicAdd(&q[d.w], a3);
}

// ---------------------------------------------------------------------------
// 4. Node update layer 0: A1 = t0 + deg*(b0 + wd0.z0)   (A0 = 0, q0 = 0)
//    Also writes the x-half of the output (out_x = z0) — fused copy.
// ---------------------------------------------------------------------------
__global__ void node0_kernel(const float4* __restrict__ z0,
                             const float4* __restrict__ T,
                             float* __restrict__ A,
                             float4* __restrict__ out) {
    int n = blockIdx.x * blockDim.x + threadIdx.x;
    if (n >= N_NODES) return;
    const float* wc = g_wc;  // layer 0
    float4 z = z0[n];
    float4 tt = T[n];
    float pd = wc[12] + wc[4]*z.x + wc[5]*z.y + wc[6]*z.z + wc[7]*z.w;
    A[n] = tt.x + tt.w * pd;
    out[N_NODES + n] = z;     // x output
}

// ---------------------------------------------------------------------------
// 5. Node update layer 1: A2 = A1 + t1 + sA1*q1 + deg*(b1 + wd1.z0 + sB1*A1)
// ---------------------------------------------------------------------------
__global__ void node_update1_kernel(const float4* __restrict__ z0,
                                    const float4* __restrict__ T,
                                    const float* __restrict__ q,
                                    float* __restrict__ A) {
    int n = blockIdx.x * blockDim.x + threadIdx.x;
    if (n >= N_NODES) return;
    const float* wc = g_wc + 16;  // layer 1
    float4 z = z0[n];
    float4 tt = T[n];
    float  a = A[n];
    float pd = wc[12] + wc[4]*z.x + wc[5]*z.y + wc[6]*z.z + wc[7]*z.w + wc[14]*a;
    A[n] = a + tt.y + wc[13] * q[n] + tt.w * pd;
}

// ---------------------------------------------------------------------------
// 6. Node update layer 2 + finalize:
//    A3 = A2 + t2 + sA2*q2 + deg*(b2 + wd2.z0 + sB2*A2);  out_z = z0 + A3
// ---------------------------------------------------------------------------
__global__ void node_update2_final_kernel(const float4* __restrict__ z0,
                                          const float4* __restrict__ T,
                                          const float* __restrict__ q,
                                          const float* __restrict__ A,
                                          float4* __restrict__ out) {
    int n = blockIdx.x * blockDim.x + threadIdx.x;
    if (n >= N_NODES) return;
    const float* wc = g_wc + 32;  // layer 2
    float4 z = z0[n];
    float4 tt = T[n];
    float  a = A[n];
    float pd = wc[12] + wc[4]*z.x + wc[5]*z.y + wc[6]*z.z + wc[7]*z.w + wc[14]*a;
    float a3 = a + tt.z + wc[13] * q[n] + tt.w * pd;
    out[n] = make_float4(z.x + a3, z.y + a3, z.z + a3, z.w + a3);
}

// ---------------------------------------------------------------------------
extern "C" void kernel_launch(void* const* d_in, const int* in_sizes, int n_in,
                              void* d_out, int out_size) {
    const float* z    = (const float*)d_in[0];
    const float* r    = (const float*)d_in[1];
    const float* rhat = (const float*)d_in[2];
    const float* W    = (const float*)d_in[3];
    const float* b    = (const float*)d_in[4];
    const int*   src  = (const int*)d_in[5];
    const int*   dst  = (const int*)d_in[6];
    float* out = (float*)d_out;

    float4 *T; float *A, *q1, *q2;
    cudaGetSymbolAddress((void**)&T,  g_T);
    cudaGetSymbolAddress((void**)&A,  g_A);
    cudaGetSymbolAddress((void**)&q1, g_q1);
    cudaGetSymbolAddress((void**)&q2, g_q2);

    const int NODE_BLOCKS = (N_NODES + 255) / 256;
    const int EDGE_BLOCKS = (N_EDGES / 4 + 255) / 256;

    init_kernel<<<NODE_BLOCKS, 256>>>(W, b, T, q1, q2);

    heavy_edge_kernel<<<EDGE_BLOCKS, 256>>>((const int4*)src, (const int4*)dst,
                                            (const float4*)r, (const float4*)rhat,
                                            (const float4*)z, T);

    node0_kernel<<<NODE_BLOCKS, 256>>>((const float4*)z, T, A, (float4*)out);

    light_edge_kernel<<<EDGE_BLOCKS, 256>>>((const int4*)src, (const int4*)dst, A, q1);
    node_update1_kernel<<<NODE_BLOCKS, 256>>>((const float4*)z, T, q1, A);

    light_edge_kernel<<<EDGE_BLOCKS, 256>>>((const int4*)src, (const int4*)dst, A, q2);
    node_update2_final_kernel<<<NODE_BLOCKS, 256>>>((const float4*)z, T, q2, A,
                                                    (float4*)out);
}